// round 1
// baseline (speedup 1.0000x reference)
#include <cuda_runtime.h>

#define DD 128
#define NMAX 50176
#define EMAX 800256
#define NBMAX 64

// Scratch (static __device__ arrays per allocation rules)
__device__ float g_bufs[2][(size_t)NMAX * DD];   // [0]=post-linear h (ht), [1]=aggregated h
__device__ float g_sl[NMAX], g_sr[NMAX];
__device__ int   g_deg[NMAX];
__device__ int   g_off[NMAX + 1];
__device__ int   g_pos[NMAX];
__device__ int   g_bsum[NBMAX];
__device__ int   g_col[EMAX];

// ---------------- CSR build ----------------

__global__ void k_zero(int N) {
    int i = blockIdx.x * blockDim.x + threadIdx.x;
    if (i < N) g_deg[i] = 0;
}

__global__ void k_count(const int* __restrict__ src, int E) {
    int e = blockIdx.x * blockDim.x + threadIdx.x;
    if (e < E) atomicAdd(&g_deg[src[e]], 1);
}

__global__ void k_scanA(int N) {
    __shared__ int sh[1024];
    int i = blockIdx.x * 1024 + threadIdx.x;
    int v = (i < N) ? g_deg[i] : 0;
    sh[threadIdx.x] = v;
    __syncthreads();
    for (int o = 1; o < 1024; o <<= 1) {
        int t = (threadIdx.x >= (unsigned)o) ? sh[threadIdx.x - o] : 0;
        __syncthreads();
        sh[threadIdx.x] += t;
        __syncthreads();
    }
    if (i < N) g_off[i] = sh[threadIdx.x] - v;   // block-local exclusive
    if (threadIdx.x == 1023) g_bsum[blockIdx.x] = sh[1023];
}

__global__ void k_scanB(int nb) {
    if (threadIdx.x == 0) {
        int run = 0;
        for (int b = 0; b < nb; b++) { int t = g_bsum[b]; g_bsum[b] = run; run += t; }
    }
}

__global__ void k_scanC(int N, int E) {
    int i = blockIdx.x * blockDim.x + threadIdx.x;
    if (i < N) {
        int v = g_off[i] + g_bsum[i >> 10];
        g_off[i] = v;
        g_pos[i] = v;
    } else if (i == N) {
        g_off[N] = E;
    }
}

__global__ void k_scatter(const int* __restrict__ src, const int* __restrict__ dst, int E) {
    int e = blockIdx.x * blockDim.x + threadIdx.x;
    if (e < E) {
        int p = atomicAdd(&g_pos[src[e]], 1);
        g_col[p] = dst[e];
    }
}

// ---------------- GEMM + leaky_relu + attention dots ----------------
// out[row][c] = leaky_relu(sum_k in[row][k] * W[k][c] + b[c], 0.2)
// g_sl[row] = dot(out[row], aw[0:128]); g_sr[row] = dot(out[row], aw[128:256])
// Block: 256 threads, 64 rows/block. Warp owns 8 full rows; lane owns 4 cols.

__global__ __launch_bounds__(256) void k_gemm(
    const float* __restrict__ xext, int in_sel,
    const float* __restrict__ W, const float* __restrict__ bias,
    const float* __restrict__ aw, int M)
{
    const float* in = (in_sel < 0) ? xext : g_bufs[in_sel];
    __shared__ float ws[64 * 128];   // 32 KB  W chunk [64k x 128n]
    __shared__ float hs[64 * 64];    // 16 KB  h tile  [64rows x 64k] (reads are broadcast)

    int tid = threadIdx.x, warp = tid >> 5, lane = tid & 31;
    int r0 = blockIdx.x * 64;
    int c4 = lane * 4;

    float4 acc[8];
#pragma unroll
    for (int r = 0; r < 8; r++) acc[r] = make_float4(0.f, 0.f, 0.f, 0.f);

    for (int kc = 0; kc < DD; kc += 64) {
        // W chunk: rows kc..kc+63, contiguous 8192 floats
        const float4* wsrc = (const float4*)(W + (size_t)kc * DD);
        float4* wdst = (float4*)ws;
#pragma unroll
        for (int i = 0; i < 8; i++) wdst[tid + i * 256] = wsrc[tid + i * 256];
        // h tile: 64 rows x 64 k
#pragma unroll
        for (int i = 0; i < 4; i++) {
            int idx = tid + i * 256;          // float4 index 0..1023
            int row = idx >> 4;
            int c = idx & 15;
            float4 v = make_float4(0.f, 0.f, 0.f, 0.f);
            if (r0 + row < M)
                v = *(const float4*)(in + (size_t)(r0 + row) * DD + kc + c * 4);
            *(float4*)(hs + row * 64 + c * 4) = v;
        }
        __syncthreads();

        int wr = warp * 8;
#pragma unroll 8
        for (int k = 0; k < 64; k++) {
            float4 w4 = *(const float4*)(ws + k * DD + c4);
#pragma unroll
            for (int r = 0; r < 8; r++) {
                float a = hs[(wr + r) * 64 + k];
                acc[r].x += a * w4.x;
                acc[r].y += a * w4.y;
                acc[r].z += a * w4.z;
                acc[r].w += a * w4.w;
            }
        }
        __syncthreads();
    }

    float4 bb = *(const float4*)(bias + c4);
    float4 al = *(const float4*)(aw + c4);
    float4 ar = *(const float4*)(aw + DD + c4);
    float* out = g_bufs[0];

#pragma unroll
    for (int r = 0; r < 8; r++) {
        int row = r0 + warp * 8 + r;      // uniform across warp
        if (row < M) {
            float4 v;
            v.x = acc[r].x + bb.x; v.x = v.x > 0.f ? v.x : 0.2f * v.x;
            v.y = acc[r].y + bb.y; v.y = v.y > 0.f ? v.y : 0.2f * v.y;
            v.z = acc[r].z + bb.z; v.z = v.z > 0.f ? v.z : 0.2f * v.z;
            v.w = acc[r].w + bb.w; v.w = v.w > 0.f ? v.w : 0.2f * v.w;
            *(float4*)(out + (size_t)row * DD + c4) = v;
            float dl = v.x * al.x + v.y * al.y + v.z * al.z + v.w * al.w;
            float dr = v.x * ar.x + v.y * ar.y + v.z * ar.z + v.w * ar.w;
#pragma unroll
            for (int o = 16; o; o >>= 1) {
                dl += __shfl_xor_sync(0xffffffffu, dl, o);
                dr += __shfl_xor_sync(0xffffffffu, dr, o);
            }
            if (lane == 0) { g_sl[row] = dl; g_sr[row] = dr; }
        }
    }
}

// ---------------- Per-node softmax + aggregation ----------------
// One warp per source node: online softmax over its CSR edge segment (no atomics),
// then edge-serial accumulation of alpha * h[dst] rows (32 lanes x float4 = 512B/row).

__global__ __launch_bounds__(256) void k_agg(
    float* __restrict__ extout, int out_sel,
    const float* __restrict__ abp, int N)
{
    const float* ht = g_bufs[0];
    float* out = (out_sel < 0) ? extout : g_bufs[out_sel];

    int gw = (blockIdx.x * blockDim.x + threadIdx.x) >> 5;
    int lane = threadIdx.x & 31;
    if (gw >= N) return;

    int base = g_off[gw], end = g_off[gw + 1];
    int c4 = lane * 4;
    float4 acc = make_float4(0.f, 0.f, 0.f, 0.f);

    if (end > base) {
        float ab = *abp;
        float sli = g_sl[gw];

        // pass 1: online softmax stats, lanes strided over edges
        float m = -1e30f, s = 0.f;
        for (int k = base + lane; k < end; k += 32) {
            int d = g_col[k];
            float e = sli + g_sr[d] + ab;
            if (e > m) { s = s * __expf(m - e) + 1.f; m = e; }
            else        { s += __expf(e - m); }
        }
#pragma unroll
        for (int o = 16; o; o >>= 1) {
            float mo = __shfl_xor_sync(0xffffffffu, m, o);
            float so = __shfl_xor_sync(0xffffffffu, s, o);
            float mn = fmaxf(m, mo);
            s = s * __expf(m - mn) + so * __expf(mo - mn);
            m = mn;
        }
        float inv = 1.f / s;
        float cshift = sli + ab - m;

        // pass 2: weighted accumulate, warp-per-edge-row
        for (int k = base; k < end; k++) {
            int d = g_col[k];
            float w = __expf(cshift + g_sr[d]) * inv;
            float4 hv = *(const float4*)(ht + (size_t)d * DD + c4);
            acc.x += w * hv.x;
            acc.y += w * hv.y;
            acc.z += w * hv.z;
            acc.w += w * hv.w;
        }
    }
    acc.x = fmaxf(acc.x, 0.f);
    acc.y = fmaxf(acc.y, 0.f);
    acc.z = fmaxf(acc.z, 0.f);
    acc.w = fmaxf(acc.w, 0.f);
    *(float4*)(out + (size_t)gw * DD + c4) = acc;
}

// ---------------- launch ----------------

extern "C" void kernel_launch(void* const* d_in, const int* in_sizes, int n_in,
                              void* d_out, int out_size)
{
    const float* x      = (const float*)d_in[0];
    const int*   esrc   = (const int*)d_in[1];
    const int*   edst   = (const int*)d_in[2];
    const float* lin_w  = (const float*)d_in[3];
    const float* lin_b  = (const float*)d_in[4];
    const float* attn_w = (const float*)d_in[5];
    const float* attn_b = (const float*)d_in[6];

    int N = in_sizes[0] / DD;
    int E = in_sizes[1];
    int nb = (N + 1023) / 1024;

    // CSR build (once; edges are layer-invariant)
    k_zero<<<(N + 255) / 256, 256>>>(N);
    k_count<<<(E + 255) / 256, 256>>>(esrc, E);
    k_scanA<<<nb, 1024>>>(N);
    k_scanB<<<1, 32>>>(nb);
    k_scanC<<<(N + 256) / 256, 256>>>(N, E);
    k_scatter<<<(E + 255) / 256, 256>>>(esrc, edst, E);

    int gB = (N + 63) / 64;
    int aB = (N + 7) / 8;
    for (int l = 0; l < 3; l++) {
        int in_sel = (l == 0) ? -1 : 1;
        k_gemm<<<gB, 256>>>(x, in_sel,
                            lin_w + (size_t)l * DD * DD,
                            lin_b + (size_t)l * DD,
                            attn_w + (size_t)l * 2 * DD, N);
        int out_sel = (l == 2) ? -1 : 1;
        k_agg<<<aB, 256>>>((float*)d_out, out_sel, attn_b + l, N);
    }
}